// round 17
// baseline (speedup 1.0000x reference)
#include <cuda_runtime.h>
#include <cuda_fp16.h>
#include <math.h>
#include <stdint.h>

// ---------------- problem constants ----------------
#define Bsz 8192
#define Dd  1024
#define Uu  512
#define Ff  4
#define Ee  4
#define Tt  2
#define Gg  5
#define NEXP 17

// ---------------- scratch ----------------
__device__ __half g_common[Bsz * Uu];                 // fp16 intermediates
__device__ __half g_field [Bsz * Ff * Uu];
__device__ float  g_logits[Bsz * Tt * Gg];
__device__ int    g_idx[Ff * Ee][Bsz];
__device__ int    g_cnt[Ff * Ee];
__device__ __half g_xh[Bsz * Dd];                     // fp16 x
__device__ __half g_wh[(size_t)NEXP * Uu * Dd];       // fp16 W, transposed [ez][u][d]

// ---------------- GEMM config: CTA 128x128, 8 warps (64x32), 2 CTAs/SM, 3-stage ----
#define BM 128
#define BN 128
#define NCH 16
#define AOF 0
#define BOF 16384
#define STAGE 32768
#define NSTG 3
#define IDX_OFF (NSTG * STAGE)
#define DSM_TOTAL (NSTG * STAGE + 1024)

#define SWZ(o) ((o) ^ (((o) >> 3) & 0x70))

__device__ __forceinline__ uint32_t s2u(const void* p) {
    return (uint32_t)__cvta_generic_to_shared(p);
}

__device__ __forceinline__ void cpa16(uint32_t dst, const void* src) {
    asm volatile("cp.async.cg.shared.global [%0], [%1], 16;"
                 :: "r"(dst), "l"(__cvta_generic_to_global(src)));
}
#define CP_COMMIT() asm volatile("cp.async.commit_group;" ::: "memory")
#define CP_WAIT(n)  asm volatile("cp.async.wait_group %0;" :: "n"(n) : "memory")

__device__ __forceinline__ void ldsm4(uint32_t* r, uint32_t addr) {
    asm volatile("ldmatrix.sync.aligned.m8n8.x4.shared.b16 {%0,%1,%2,%3}, [%4];"
                 : "=r"(r[0]), "=r"(r[1]), "=r"(r[2]), "=r"(r[3]) : "r"(addr));
}

__device__ __forceinline__ void mma16816(float* c, const uint32_t* a, uint32_t b0, uint32_t b1) {
    asm volatile(
        "mma.sync.aligned.m16n8k16.row.col.f32.f16.f16.f32 "
        "{%0,%1,%2,%3}, {%4,%5,%6,%7}, {%8,%9}, {%0,%1,%2,%3};"
        : "+f"(c[0]), "+f"(c[1]), "+f"(c[2]), "+f"(c[3])
        : "r"(a[0]), "r"(a[1]), "r"(a[2]), "r"(a[3]), "r"(b0), "r"(b1));
}

// issue one k-chunk (64 k-elems): A 128x128B + B 128x128B
__device__ __forceinline__ void issue_chunk(uint32_t sb, int ch,
                                            const __half* __restrict__ wb,
                                            const int* __restrict__ sidx,
                                            int m0, int n0, int tid)
{
    uint32_t st = sb + (uint32_t)(ch % NSTG) * STAGE;
    const int kbase = ch * 64;
#pragma unroll
    for (int i = 0; i < 4; i++) {
        int u = tid + i * 256, r = u >> 3, cc = u & 7;
        int grow = sidx ? sidx[r] : (m0 + r);
        size_t go = (size_t)grow * Dd + kbase + cc * 8;
        cpa16(st + AOF + SWZ(r * 128 + cc * 16), g_xh + go);
    }
#pragma unroll
    for (int i = 0; i < 4; i++) {
        int u = tid + i * 256, r = u >> 3, cc = u & 7;
        size_t go = (size_t)(n0 + r) * Dd + kbase + cc * 8;
        cpa16(st + BOF + SWZ(r * 128 + cc * 16), wb + go);
    }
    CP_COMMIT();
}

// ============================================================
// prep
// ============================================================
__global__ void zero_cnt()
{
    if (threadIdx.x < Ff * Ee) g_cnt[threadIdx.x] = 0;
}

#define PREP_BLOCKS (Bsz / 8)                 // 1024
#define SPLITW_BLOCKS (16 * 32 * NEXP)        // 8704

// merged prep: blocks [0,1024) per-row prep; rest transpose+convert W
__global__ __launch_bounds__(256) void prep_merged(
    const float* __restrict__ x, const float* __restrict__ Wg,
    const float* __restrict__ bg,
    const float* __restrict__ Wc, const float* __restrict__ We)
{
    __shared__ float smem_f[Dd * Tt * Gg];
    const int tid = threadIdx.x;

    if (blockIdx.x < PREP_BLOCKS) {
        float* wgs = smem_f;
        for (int i = tid; i < Dd * Tt * Gg; i += 256) {
            int d = i / (Tt * Gg), tg = i - d * (Tt * Gg);
            int t = tg / Gg, g = tg - t * Gg;
            wgs[i] = Wg[((size_t)t * Dd + d) * Gg + g];
        }
        __syncthreads();

        const int w = tid >> 5, lane = tid & 31;
        const int b = blockIdx.x * 8 + w;
        const float* xr = x + (size_t)b * Dd;

        float acc[Tt * Gg];
#pragma unroll
        for (int j = 0; j < Tt * Gg; j++) acc[j] = 0.f;

#pragma unroll
        for (int j = 0; j < 8; j++) {
            int k4 = lane + j * 32;
            float4 v = ((const float4*)xr)[k4];
            __half2* dst = (__half2*)(g_xh + (size_t)b * Dd + k4 * 4);
            dst[0] = __floats2half2_rn(v.x, v.y);
            dst[1] = __floats2half2_rn(v.z, v.w);
            const float* wr = wgs + (k4 * 4) * (Tt * Gg);
            float vv[4] = {v.x, v.y, v.z, v.w};
#pragma unroll
            for (int q = 0; q < 4; q++)
#pragma unroll
                for (int jj = 0; jj < Tt * Gg; jj++)
                    acc[jj] = fmaf(vv[q], wr[q * (Tt * Gg) + jj], acc[jj]);
        }
#pragma unroll
        for (int jj = 0; jj < Tt * Gg; jj++)
#pragma unroll
            for (int o = 16; o; o >>= 1) acc[jj] += __shfl_xor_sync(0xffffffffu, acc[jj], o);
        if (lane < Tt * Gg)
            g_logits[(size_t)b * (Tt * Gg) + lane] = acc[lane] + bg[lane];

        uint4* zp = (uint4*)(g_field + (size_t)b * (Ff * Uu));
#pragma unroll
        for (int j = 0; j < 4; j++) zp[lane + j * 32] = make_uint4(0u, 0u, 0u, 0u);

        if (lane < 8) {
            if (xr[lane] > 0.f) {
                int p = atomicAdd(&g_cnt[lane], 1);
                g_idx[lane][p] = b;
            }
        } else if (lane < 10) {
            int f = 2 + (lane - 8);
            float v = xr[8 + (lane - 8)];
            int e = (v <= -0.5f) ? 0 : (v <= 0.f) ? 1 : (v <= 0.5f) ? 2 : 3;
            int fe = f * 4 + e;
            int p = atomicAdd(&g_cnt[fe], 1);
            g_idx[fe][p] = b;
        }
    } else {
        float (*t)[33] = (float(*)[33])smem_f;
        int i = blockIdx.x - PREP_BLOCKS;
        int ez = i >> 9;
        int rem = i & 511;
        int u0 = (rem & 15) * 32;
        int d0 = (rem >> 4) * 32;
        const float* src = (ez == 0) ? Wc : (We + (size_t)(ez - 1) * Dd * Uu);
        int tx = tid & 31, ty = tid >> 5;
#pragma unroll
        for (int k = 0; k < 32; k += 8)
            t[ty + k][tx] = src[(size_t)(d0 + ty + k) * Uu + u0 + tx];
        __syncthreads();
#pragma unroll
        for (int k = 0; k < 32; k += 8) {
            int u = u0 + ty + k, d = d0 + tx;
            g_wh[(size_t)ez * Uu * Dd + (size_t)u * Dd + d] = __float2half_rn(t[tx][ty + k]);
        }
    }
}

// ============================================================
// GEMM mainloop: single fp16 pass, warp tile 64x32, 3-stage pipeline
// ============================================================
__device__ __forceinline__ void gemm_mainloop(
    uint32_t sb, const __half* wb, const int* sidx,
    int m0, int n0, int tid, int lane, int wm, int wn,
    float acc[4][4][4])
{
    const int lrow = (lane & 7) + ((lane >> 3) & 1) * 8;
    const int kb   = lane >> 4;

    issue_chunk(sb, 0, wb, sidx, m0, n0, tid);
    issue_chunk(sb, 1, wb, sidx, m0, n0, tid);

    for (int ch = 0; ch < NCH; ch++) {
        // prefetch 2 ahead; stage (ch+2)%3 == (ch-1)%3, whose reads finished
        // at the end-of-iteration barrier of ch-1
        if (ch + 2 < NCH) {
            issue_chunk(sb, ch + 2, wb, sidx, m0, n0, tid);
            CP_WAIT(2);
        } else if (ch + 1 < NCH) {
            CP_WAIT(1);
        } else {
            CP_WAIT(0);
        }
        __syncthreads();

        uint32_t s0 = sb + (uint32_t)(ch % NSTG) * STAGE;
#pragma unroll
        for (int ks = 0; ks < 4; ks++) {
            uint32_t koff = (uint32_t)(ks * 2 + kb) * 16;
            uint32_t af[4][4], bf[2][4];
#pragma unroll
            for (int mi = 0; mi < 4; mi++) {
                uint32_t ro = (uint32_t)(wm + mi * 16 + lrow) * 128 + koff;
                ldsm4(af[mi], s0 + AOF + SWZ(ro));
            }
#pragma unroll
            for (int nj = 0; nj < 2; nj++) {
                uint32_t ro = (uint32_t)(wn + nj * 16 + lrow) * 128 + koff;
                ldsm4(bf[nj], s0 + BOF + SWZ(ro));
            }
#pragma unroll
            for (int mi = 0; mi < 4; mi++)
#pragma unroll
                for (int nj = 0; nj < 2; nj++) {
                    mma16816(acc[mi][2*nj],   af[mi], bf[nj][0], bf[nj][2]);
                    mma16816(acc[mi][2*nj+1], af[mi], bf[nj][1], bf[nj][3]);
                }
        }
        __syncthreads();
    }
}

// ---------------- merged GEMM: z=0 common (dense), z>=1 expert (gathered) ----
__global__ __launch_bounds__(256, 2) void gemm_all(
    const float* __restrict__ bc, const float* __restrict__ be)
{
    extern __shared__ __align__(1024) char dsm[];
    const int z = blockIdx.z;
    const bool dense = (z == 0);
    const int fe = z - 1;
    const int t0 = blockIdx.x * BM;
    int cnt = 0;
    if (!dense) {
        cnt = g_cnt[fe];
        if (t0 >= cnt) return;
    }

    const int tid = threadIdx.x;
    const int w = tid >> 5, lane = tid & 31;
    const int n0 = blockIdx.y * BN;
    const int wm = (w & 1) * 64;
    const int wn = (w >> 1) * 32;
    uint32_t sb = s2u(dsm);
    int* sidx = (int*)(dsm + IDX_OFF);

    if (!dense) {
        if (tid < BM) {
            int s = t0 + tid;
            sidx[tid] = g_idx[fe][(s < cnt) ? s : (cnt - 1)];
        }
        __syncthreads();
    }

    const int ez = dense ? 0 : (1 + fe);
    const __half* wb = g_wh + (size_t)ez * Uu * Dd;

    float acc[4][4][4];
#pragma unroll
    for (int mi = 0; mi < 4; mi++)
#pragma unroll
        for (int ni = 0; ni < 4; ni++)
#pragma unroll
            for (int j = 0; j < 4; j++) acc[mi][ni][j] = 0.f;

    gemm_mainloop(sb, wb, dense ? nullptr : sidx, t0, n0, tid, lane, wm, wn, acc);

    if (dense) {
        const float* bep = bc + n0;
#pragma unroll
        for (int mi = 0; mi < 4; mi++) {
#pragma unroll
            for (int h = 0; h < 2; h++) {
                int rl = wm + mi * 16 + (lane >> 2) + h * 8;
                __half* gp = g_common + (size_t)(t0 + rl) * Uu + n0;
#pragma unroll
                for (int ni = 0; ni < 4; ni++) {
                    int cl = wn + ni * 8 + (lane & 3) * 2;
                    float v0 = fmaxf(acc[mi][ni][h * 2 + 0] + bep[cl],     0.f);
                    float v1 = fmaxf(acc[mi][ni][h * 2 + 1] + bep[cl + 1], 0.f);
                    *(__half2*)(gp + cl) = __floats2half2_rn(v0, v1);
                }
            }
        }
    } else {
        const int f = fe >> 2;
        const float* bep = be + (size_t)fe * Uu + n0;
        const bool atom = (f < 2);
#pragma unroll
        for (int mi = 0; mi < 4; mi++) {
#pragma unroll
            for (int h = 0; h < 2; h++) {
                int rl = wm + mi * 16 + (lane >> 2) + h * 8;
                if (t0 + rl >= cnt) continue;
                int grow = sidx[rl];
                __half* gp = g_field + (size_t)grow * (Ff * Uu) + (size_t)f * Uu + n0;
#pragma unroll
                for (int ni = 0; ni < 4; ni++) {
                    int cl = wn + ni * 8 + (lane & 3) * 2;
                    float v0 = fmaxf(acc[mi][ni][h * 2 + 0] + bep[cl],     0.f);
                    float v1 = fmaxf(acc[mi][ni][h * 2 + 1] + bep[cl + 1], 0.f);
                    __half2 hv = __floats2half2_rn(v0, v1);
                    if (atom) atomicAdd((__half2*)(gp + cl), hv);
                    else      *(__half2*)(gp + cl) = hv;
                }
            }
        }
    }
}

// ============================================================
// epilogue: warp-per-row, software-pipelined (double-buffered rows)
// ============================================================
#define EPI_BLOCKS 296
#define EPI_STRIDE (EPI_BLOCKS * 8)

__device__ __forceinline__ void epi_load(int b, int lane,
                                         __half2 ch[8], __half2 fh[32], float& lgv)
{
    const __half2* cp = (const __half2*)(g_common + (size_t)b * Uu);
#pragma unroll
    for (int j = 0; j < 8; j++) ch[j] = cp[lane + 32 * j];
    const __half2* fp = (const __half2*)(g_field + (size_t)b * Ff * Uu);
#pragma unroll
    for (int j = 0; j < 32; j++) fh[j] = fp[lane + 32 * j];
    lgv = (lane < Tt * Gg) ? g_logits[(size_t)b * (Tt * Gg) + lane] : 0.f;
}

__device__ __forceinline__ void epi_compute(
    int b, int lane, const __half2 ch[8], const __half2 fh[32], float lgv,
    const float* wa_s, const float* wu_s,
    const float* __restrict__ ba, const float* __restrict__ bu,
    float* __restrict__ out)
{
    float sa[Ff] = {0.f, 0.f, 0.f, 0.f}, su[Ff] = {0.f, 0.f, 0.f, 0.f};
#pragma unroll
    for (int j = 0; j < 8; j++) {
        float2 v = __half22float2(ch[j]);
        int u0 = 2 * (lane + 32 * j);
#pragma unroll
        for (int f = 0; f < Ff; f++) {
            sa[f] = fmaf(v.x, wa_s[f * 1024 + u0],     sa[f]);
            sa[f] = fmaf(v.y, wa_s[f * 1024 + u0 + 1], sa[f]);
            su[f] = fmaf(v.x, wu_s[f * 1024 + u0],     su[f]);
            su[f] = fmaf(v.y, wu_s[f * 1024 + u0 + 1], su[f]);
        }
    }
#pragma unroll
    for (int j2 = 0; j2 < 32; j2++) {
        int f = j2 >> 3;
        int u0 = 2 * (lane + 32 * (j2 & 7));
        float2 v = __half22float2(fh[j2]);
        sa[f] = fmaf(v.x, wa_s[f * 1024 + 512 + u0],     sa[f]);
        sa[f] = fmaf(v.y, wa_s[f * 1024 + 512 + u0 + 1], sa[f]);
        su[f] = fmaf(v.x, wu_s[f * 1024 + 512 + u0],     su[f]);
        su[f] = fmaf(v.y, wu_s[f * 1024 + 512 + u0 + 1], su[f]);
    }
#pragma unroll
    for (int f = 0; f < Ff; f++) {
#pragma unroll
        for (int o = 16; o; o >>= 1) {
            sa[f] += __shfl_xor_sync(0xffffffffu, sa[f], o);
            su[f] += __shfl_xor_sync(0xffffffffu, su[f], o);
        }
        sa[f] = 1.f / (1.f + expf(-(sa[f] + ba[f])));
        su[f] = 1.f / (1.f + expf(-(su[f] + bu[f])));
    }

    float lg[Tt * Gg];
#pragma unroll
    for (int j = 0; j < Tt * Gg; j++) lg[j] = __shfl_sync(0xffffffffu, lgv, j);
    float gates[Tt][Gg];
#pragma unroll
    for (int t = 0; t < Tt; t++) {
        float mx = lg[t * Gg];
#pragma unroll
        for (int g = 1; g < Gg; g++) mx = fmaxf(mx, lg[t * Gg + g]);
        float sum = 0.f;
#pragma unroll
        for (int g = 0; g < Gg; g++) { gates[t][g] = expf(lg[t * Gg + g] - mx); sum += gates[t][g]; }
        float inv = 1.f / sum;
#pragma unroll
        for (int g = 0; g < Gg; g++) gates[t][g] *= inv;
    }

    float2* o0p = (float2*)(out + ((size_t)b * Tt + 0) * Uu);
    float2* o1p = (float2*)(out + ((size_t)b * Tt + 1) * Uu);
#pragma unroll
    for (int j = 0; j < 8; j++) {
        float2 c = __half22float2(ch[j]);
        float a0 = gates[0][0] * c.x, b0 = gates[0][0] * c.y;
        float a1 = gates[1][0] * c.x, b1 = gates[1][0] * c.y;
#pragma unroll
        for (int f = 0; f < Ff; f++) {
            float2 fo = __half22float2(fh[f * 8 + j]);
            float fx = su[f] * (sa[f] * fo.x) + (1.f - su[f]) * c.x;
            float fy = su[f] * (sa[f] * fo.y) + (1.f - su[f]) * c.y;
            a0 = fmaf(gates[0][1 + f], fx, a0);
            b0 = fmaf(gates[0][1 + f], fy, b0);
            a1 = fmaf(gates[1][1 + f], fx, a1);
            b1 = fmaf(gates[1][1 + f], fy, b1);
        }
        o0p[lane + 32 * j] = make_float2(a0, b0);
        o1p[lane + 32 * j] = make_float2(a1, b1);
    }
}

__global__ __launch_bounds__(256, 2) void epilogue_kernel(
    const float* __restrict__ Wa, const float* __restrict__ ba,
    const float* __restrict__ Wu, const float* __restrict__ bu,
    float* __restrict__ out)
{
    __shared__ float wa_s[Ff * 2 * Uu];   // 16KB
    __shared__ float wu_s[Ff * 2 * Uu];   // 16KB
    const int tid = threadIdx.x;
    for (int i = tid; i < Ff * 2 * Uu; i += 256) {
        wa_s[i] = Wa[i];
        wu_s[i] = Wu[i];
    }
    __syncthreads();

    const int w = tid >> 5, lane = tid & 31;

    __half2 chA[8], fhA[32], chB[8], fhB[32];
    float lgA, lgB;

    int b = blockIdx.x * 8 + w;
    if (b >= Bsz) return;
    epi_load(b, lane, chA, fhA, lgA);

    while (true) {
        int bB = b + EPI_STRIDE;
        bool hasB = (bB < Bsz);
        if (hasB) epi_load(bB, lane, chB, fhB, lgB);       // overlap with A compute
        epi_compute(b, lane, chA, fhA, lgA, wa_s, wu_s, ba, bu, out);
        if (!hasB) break;

        int bA = bB + EPI_STRIDE;
        bool hasA = (bA < Bsz);
        if (hasA) epi_load(bA, lane, chA, fhA, lgA);       // overlap with B compute
        epi_compute(bB, lane, chB, fhB, lgB, wa_s, wu_s, ba, bu, out);
        if (!hasA) break;
        b = bA;
    }
}

// ============================================================
// launch
// ============================================================
extern "C" void kernel_launch(void* const* d_in, const int* in_sizes, int n_in,
                              void* d_out, int out_size)
{
    const float* x  = (const float*)d_in[0];
    const float* Wc = (const float*)d_in[1];
    const float* bc = (const float*)d_in[2];
    const float* We = (const float*)d_in[3];
    const float* be = (const float*)d_in[4];
    const float* Wg = (const float*)d_in[5];
    const float* bg = (const float*)d_in[6];
    const float* Wa = (const float*)d_in[7];
    const float* ba = (const float*)d_in[8];
    const float* Wu = (const float*)d_in[9];
    const float* bu = (const float*)d_in[10];
    float* out = (float*)d_out;

    cudaFuncSetAttribute(gemm_all, cudaFuncAttributeMaxDynamicSharedMemorySize, DSM_TOTAL);

    zero_cnt<<<1, 32>>>();
    prep_merged<<<PREP_BLOCKS + SPLITW_BLOCKS, 256>>>(x, Wg, bg, Wc, We);
    gemm_all<<<dim3(Bsz / BM, Uu / BN, 1 + Ff * Ee), 256, DSM_TOTAL>>>(bc, be);
    epilogue_kernel<<<EPI_BLOCKS, 256>>>(Wa, ba, Wu, bu, out);
}